// round 1
// baseline (speedup 1.0000x reference)
#include <cuda_runtime.h>

#define N_B 16
#define IC  256
#define OC  256
#define HH  64
#define WW  64
#define SD  512
#define EPSV 1e-8f

// ---- scratch (device globals; no allocations allowed) ----
__device__ float g_m[N_B * IC];          // (style @ mod_w^T + bias) + 1
__device__ float g_demod[N_B * OC];      // rsqrt(sum_i m^2 * wsq + eps)
__device__ float g_wsq[IC * OC];         // [i][o] : sum over 9 taps of weight^2
__device__ float g_wt[OC * IC * 9];      // [ocb(8)][ic(256)][tap(9)][oc32(32)]

// ---------------------------------------------------------------------------
// Kernel 1: m[n,i] = style[n] . mod_w[i] + mod_b[i] + 1
// ---------------------------------------------------------------------------
__global__ void mod_kernel(const float* __restrict__ style,
                           const float* __restrict__ mod_w,
                           const float* __restrict__ mod_b) {
    int n = blockIdx.x;
    int i = threadIdx.x;
    __shared__ float ss[SD];
    for (int k = threadIdx.x; k < SD; k += blockDim.x) ss[k] = style[n * SD + k];
    __syncthreads();
    float acc = 0.f;
    const float* wr = mod_w + i * SD;
#pragma unroll 8
    for (int k = 0; k < SD; k++) acc += ss[k] * wr[k];
    g_m[n * IC + i] = acc + mod_b[i] + 1.0f;
}

// ---------------------------------------------------------------------------
// Kernel 2: wsq[i][o] = sum_t weight[o,i,t]^2
// ---------------------------------------------------------------------------
__global__ void wsq_kernel(const float* __restrict__ weight) {
    int i = blockIdx.x;
    int o = threadIdx.x;
    const float* w = weight + (o * IC + i) * 9;
    float s = 0.f;
#pragma unroll
    for (int t = 0; t < 9; t++) s += w[t] * w[t];
    g_wsq[i * OC + o] = s;
}

// ---------------------------------------------------------------------------
// Kernel 3: demod[n,o] = rsqrt( sum_i m[n,i]^2 * wsq[i][o] + eps )
// ---------------------------------------------------------------------------
__global__ void demod_kernel() {
    int n = blockIdx.x;
    int o = threadIdx.x;
    __shared__ float ms[IC];
    ms[threadIdx.x] = g_m[n * IC + threadIdx.x];
    __syncthreads();
    float acc = EPSV;
#pragma unroll 8
    for (int i = 0; i < IC; i++) acc += ms[i] * ms[i] * g_wsq[i * OC + o];
    g_demod[n * OC + o] = rsqrtf(acc);
}

// ---------------------------------------------------------------------------
// Kernel 4: transpose weights into [ocb][ic][tap][oc32] (coalesced SMEM fills)
// ---------------------------------------------------------------------------
__global__ void wt_kernel(const float* __restrict__ weight) {
    int idx = blockIdx.x * 256 + threadIdx.x;          // 0 .. 589823
    int oc32 = idx & 31;
    int tmp  = idx >> 5;
    int tap  = tmp % 9;  tmp /= 9;
    int ic   = tmp & 255;
    int ocb  = tmp >> 8;
    int o = ocb * 32 + oc32;
    g_wt[idx] = weight[(o * IC + ic) * 9 + tap];
}

// ---------------------------------------------------------------------------
// Kernel 5: main conv. CTA tile: 32 oc x (8 rows x 32 cols) pixels.
// Thread: 4 oc x 8 px. K-loop: 32 chunks of 8 input channels,
// register-staged double buffering. Input modulation (x * m) folded into
// the SMEM fill; demod folded into the epilogue.
// ---------------------------------------------------------------------------
#define OC_T 32
#define TH 8
#define TW 32
#define ICC 8
#define XS 34                    // smem row stride (floats) -> conflict-free LDS.64
#define XROWS 10
#define XPLANE (XROWS * XS)      // 340
#define XTOT (ICC * XPLANE)      // 2720
#define WTOT (ICC * 9 * OC_T)    // 2304
#define NCHUNK (IC / ICC)        // 32

__global__ __launch_bounds__(256, 2)
void conv_kernel(const float* __restrict__ x, float* __restrict__ out) {
    __shared__ __align__(16) float xs[2][XTOT];
    __shared__ __align__(16) float ws[2][WTOT];

    const int n   = blockIdx.z;
    const int ocb = blockIdx.y;
    const int sp  = blockIdx.x;            // 0..15
    const int ht  = sp >> 1, wt = sp & 1;
    const int h0  = ht * TH, w0 = wt * TW;

    const int tid  = threadIdx.x;
    const int ocg  = tid >> 5;             // 0..7  (4 oc each)
    const int pg   = tid & 31;             // 0..31
    const int prow = pg >> 2;              // 0..7
    const int pcol = (pg & 3) << 3;        // 0,8,16,24

    const float* xbase = x + (size_t)(n * IC) * (HH * WW);
    const float* mrow  = g_m + n * IC;

    float acc[4][8];
#pragma unroll
    for (int o = 0; o < 4; o++)
#pragma unroll
        for (int p = 0; p < 8; p++) acc[o][p] = 0.f;

    float xstg[11];
    float wstg[9];

    // ---- stage chunk 0 ----
    {
        const int icb = 0;
        const float* wsrc = g_wt + (ocb * IC + icb) * 288;
#pragma unroll
        for (int k = 0; k < 9; k++) wstg[k] = wsrc[tid + k * 256];
#pragma unroll
        for (int k = 0; k < 11; k++) {
            int e = tid + k * 256;
            float v = 0.f;
            if (e < XTOT) {
                int c  = e % XS;
                int rr = (e / XS) % XROWS;
                int ic = e / XPLANE;
                int gh = h0 + rr - 1;
                int gw = w0 + c - 1;
                if ((unsigned)gh < HH && (unsigned)gw < WW)
                    v = xbase[(icb + ic) * (HH * WW) + gh * WW + gw] * mrow[icb + ic];
            }
            xstg[k] = v;
        }
    }
    // ---- commit chunk 0 -> buf 0 ----
#pragma unroll
    for (int k = 0; k < 9; k++) ws[0][tid + k * 256] = wstg[k];
#pragma unroll
    for (int k = 0; k < 11; k++) {
        int e = tid + k * 256;
        if (e < XTOT) xs[0][e] = xstg[k];
    }
    __syncthreads();

    for (int chunk = 0; chunk < NCHUNK; chunk++) {
        const int buf = chunk & 1;

        // stage next chunk into registers (overlaps with compute below)
        if (chunk + 1 < NCHUNK) {
            const int icb = (chunk + 1) * ICC;
            const float* wsrc = g_wt + (ocb * IC + icb) * 288;
#pragma unroll
            for (int k = 0; k < 9; k++) wstg[k] = wsrc[tid + k * 256];
#pragma unroll
            for (int k = 0; k < 11; k++) {
                int e = tid + k * 256;
                float v = 0.f;
                if (e < XTOT) {
                    int c  = e % XS;
                    int rr = (e / XS) % XROWS;
                    int ic = e / XPLANE;
                    int gh = h0 + rr - 1;
                    int gw = w0 + c - 1;
                    if ((unsigned)gh < HH && (unsigned)gw < WW)
                        v = xbase[(icb + ic) * (HH * WW) + gh * WW + gw] * mrow[icb + ic];
                }
                xstg[k] = v;
            }
        }

        // ---- compute on current buffer ----
#pragma unroll 2
        for (int ic = 0; ic < ICC; ic++) {
            const float* xp = &xs[buf][ic * XPLANE + prow * XS + pcol];
#pragma unroll
            for (int kh = 0; kh < 3; kh++) {
                float xv[10];
                const float2* xp2 = (const float2*)(xp + kh * XS);
#pragma unroll
                for (int j = 0; j < 5; j++) {
                    float2 t = xp2[j];
                    xv[2 * j] = t.x;
                    xv[2 * j + 1] = t.y;
                }
#pragma unroll
                for (int kw = 0; kw < 3; kw++) {
                    // warp-uniform broadcast load (ocg constant within warp)
                    const float4 wv4 = *(const float4*)&ws[buf][((ic * 3 + kh) * 3 + kw) * 32 + ocg * 4];
                    const float wv[4] = {wv4.x, wv4.y, wv4.z, wv4.w};
#pragma unroll
                    for (int o = 0; o < 4; o++)
#pragma unroll
                        for (int p = 0; p < 8; p++)
                            acc[o][p] += wv[o] * xv[kw + p];
                }
            }
        }

        // commit next chunk into the other buffer, then one barrier
        if (chunk + 1 < NCHUNK) {
            const int nb = buf ^ 1;
#pragma unroll
            for (int k = 0; k < 9; k++) ws[nb][tid + k * 256] = wstg[k];
#pragma unroll
            for (int k = 0; k < 11; k++) {
                int e = tid + k * 256;
                if (e < XTOT) xs[nb][e] = xstg[k];
            }
        }
        __syncthreads();
    }

    // ---- epilogue: scale by demod, vectorized stores ----
#pragma unroll
    for (int o = 0; o < 4; o++) {
        const int oc = ocb * 32 + ocg * 4 + o;
        const float d = g_demod[n * OC + oc];
        float* orow = out + (((size_t)(n * OC + oc)) * HH + (h0 + prow)) * WW + w0 + pcol;
        float4 v0, v1;
        v0.x = acc[o][0] * d; v0.y = acc[o][1] * d; v0.z = acc[o][2] * d; v0.w = acc[o][3] * d;
        v1.x = acc[o][4] * d; v1.y = acc[o][5] * d; v1.z = acc[o][6] * d; v1.w = acc[o][7] * d;
        ((float4*)orow)[0] = v0;
        ((float4*)orow)[1] = v1;
    }
}

// ---------------------------------------------------------------------------
extern "C" void kernel_launch(void* const* d_in, const int* in_sizes, int n_in,
                              void* d_out, int out_size) {
    const float* x      = (const float*)d_in[0];
    const float* style  = (const float*)d_in[1];
    const float* weight = (const float*)d_in[2];
    const float* mod_w  = (const float*)d_in[3];
    const float* mod_b  = (const float*)d_in[4];
    float* out = (float*)d_out;

    mod_kernel<<<N_B, 256>>>(style, mod_w, mod_b);
    wsq_kernel<<<IC, 256>>>(weight);
    demod_kernel<<<N_B, 256>>>();
    wt_kernel<<<(OC * IC * 9) / 256, 256>>>(weight);

    dim3 grid(16, 8, N_B);   // 16 spatial tiles, 8 oc tiles, 16 samples
    conv_kernel<<<grid, 256>>>(x, out);
}